// round 12
// baseline (speedup 1.0000x reference)
#include <cuda_runtime.h>
#include <cuda_fp16.h>
#include <cstdint>
#include <math.h>

// Problem constants
#define B_   2
#define CI   16
#define CO   32
#define G_   12
#define R_   12
#define S_   32
#define V_   32768          // 32^3
#define AO   384            // Co*G
#define KG1  192            // Ci*G
#define KG2  384            // Co*G
#define NY   25165824       // B*Co*G*V  (y element count)
#define CNT1 393216.0f      // G_*V_
#define CNTB 786432.0f      // B_*G_*V_

// ---------------- scratch (device globals; no allocation allowed) -------------
__device__ __half g_zh[(size_t)B_ * AO * V_];        // z1 / z2
__device__ __half g_resh[(size_t)B_ * AO * V_];      // residual
__device__ __half g_yh[(size_t)B_ * AO * V_];        // y1 / y2
__device__ float  g_w[3 * 144 * R_];
__device__ __half g_Acmb1[2 * AO * KG1];             // [K1 ; Kres]  (768 x 192)
__device__ __half g_A2[AO * KG2];                    // 384 x 384
__device__ __half g_xt[(size_t)B_ * V_ * KG1];       // x transposed fp16 [b][v][k]
__device__ __half g_yt[(size_t)B_ * V_ * KG2];       // norm(relu(y1)) transposed fp16
__device__ float  g_Krot1[AO * 27];
__device__ float  g_Krot2[AO * 27];
__device__ float  g_acc[320];  // [0:64) s1 [64:128) q1 [128:192) s2 [192:256) q2 [256:288) bs [288:320) bq

// ---------------- helpers ------------------------------------------------------
__device__ __forceinline__ uint32_t smem_u32(const void* p) {
    uint32_t a;
    asm("{ .reg .u64 t; cvta.to.shared.u64 t, %1; cvt.u32.u64 %0, t; }" : "=r"(a) : "l"(p));
    return a;
}

#define LDMATRIX_X4(r0, r1, r2, r3, addr) \
    asm volatile("ldmatrix.sync.aligned.m8n8.x4.shared.b16 {%0,%1,%2,%3}, [%4];" \
                 : "=r"(r0), "=r"(r1), "=r"(r2), "=r"(r3) : "r"(addr))
#define MMA_F16(c0, c1, c2, c3, a0, a1, a2, a3, b0, b1) \
    asm volatile("mma.sync.aligned.m16n8k16.row.col.f32.f16.f16.f32 " \
                 "{%0,%1,%2,%3}, {%4,%5,%6,%7}, {%8,%9}, {%0,%1,%2,%3};" \
                 : "+f"(c0), "+f"(c1), "+f"(c2), "+f"(c3) \
                 : "r"(a0), "r"(a1), "r"(a2), "r"(a3), "r"(b0), "r"(b1))
#define CP_ASYNC16(dst, src) \
    asm volatile("cp.async.cg.shared.global [%0], [%1], 16;" :: "r"(dst), "l"(src))
#define CP_COMMIT() asm volatile("cp.async.commit_group;" ::: "memory")
#define CP_WAIT1()  asm volatile("cp.async.wait_group 1;" ::: "memory")

// ---------------- merged setup kernel -----------------------------------------
__global__ void setup_kernel(const float* __restrict__ H,
                             const float* __restrict__ Href1,
                             const float* __restrict__ Href2,
                             const float* __restrict__ Hrefr,
                             const float* __restrict__ Ws1,
                             const float* __restrict__ Ws2) {
    int blk = blockIdx.x;
    int t = threadIdx.x;
    if (blk < 3) {
        if (t >= 144) return;
        const float* Href = (blk == 0) ? Href1 : (blk == 1) ? Href2 : Hrefr;
        float* wout = g_w + blk * 1728;
        int o = t / G_, g = t % G_;
        float M[9];
        #pragma unroll
        for (int i = 0; i < 3; i++)
            #pragma unroll
            for (int k = 0; k < 3; k++) {
                float s = 0.f;
                #pragma unroll
                for (int j = 0; j < 3; j++)
                    s += H[o*9 + j*3 + i] * H[g*9 + j*3 + k];
                M[i*3 + k] = s;
            }
        float wv[R_]; float tot = 0.f;
        #pragma unroll
        for (int r = 0; r < R_; r++) {
            float tr = 0.f;
            #pragma unroll
            for (int m = 0; m < 9; m++) tr += M[m] * Href[r*9 + m];
            float c = (tr - 1.f) * 0.5f;
            c = fminf(fmaxf(c, -1.f + 1e-6f), 1.f - 1e-6f);
            float d = acosf(c);
            float ww = expf(-2.f * d * d);
            wv[r] = ww; tot += ww;
        }
        float inv = 1.f / tot;
        #pragma unroll
        for (int r = 0; r < R_; r++) wout[t * R_ + r] = wv[r] * inv;
    } else if (blk < 5) {
        if (t >= G_ * 27) return;
        const float* Ws = (blk == 3) ? Ws1 : Ws2;
        float* Krot = (blk == 3) ? g_Krot1 : g_Krot2;
        int g = t / 27, v = t % 27;
        int d = v / 9, h = (v / 3) % 3, w = v % 3;
        float cz = (float)(d - 1), cy = (float)(h - 1), cx = (float)(w - 1);
        float pix[3];
        #pragma unroll
        for (int j = 0; j < 3; j++)
            pix[j] = cz * H[g*9 + 0*3 + j] + cy * H[g*9 + 1*3 + j] + cx * H[g*9 + 2*3 + j] + 1.0f;
        float tt[3]; int fi[3];
        #pragma unroll
        for (int j = 0; j < 3; j++) {
            float f = floorf(pix[j]);
            tt[j] = pix[j] - f;
            fi[j] = (int)f;
        }
        float wc[8]; int ic[8];
        int n = 0;
        #pragma unroll
        for (int dz = 0; dz < 2; dz++)
            #pragma unroll
            for (int dy = 0; dy < 2; dy++)
                #pragma unroll
                for (int dx = 0; dx < 2; dx++) {
                    int iz = fi[0] + dz, iy = fi[1] + dy, ix = fi[2] + dx;
                    bool valid = (iz >= 0 && iz <= 2 && iy >= 0 && iy <= 2 && ix >= 0 && ix <= 2);
                    float wz = dz ? tt[0] : 1.f - tt[0];
                    float wy = dy ? tt[1] : 1.f - tt[1];
                    float wx = dx ? tt[2] : 1.f - tt[2];
                    int cz_ = min(max(iz, 0), 2), cy_ = min(max(iy, 0), 2), cx_ = min(max(ix, 0), 2);
                    ic[n] = cz_*9 + cy_*3 + cx_;
                    wc[n] = valid ? (wz * wy * wx) : 0.f;
                    n++;
                }
        for (int c = 0; c < CO; c++) {
            float s = 0.f;
            #pragma unroll
            for (int q = 0; q < 8; q++) s += Ws[c*27 + ic[q]] * wc[q];
            Krot[(c * G_ + g) * 27 + v] = s;
        }
    } else {
        if (t < 320) g_acc[t] = 0.f;
    }
}

// merged K-matrix build
#define NK1 (AO * KG1)
#define NK2 (AO * KG2)
__global__ void computeK_all(const float* __restrict__ Wg1,
                             const float* __restrict__ Wg2,
                             const float* __restrict__ Wres) {
    int total = 2 * NK1 + NK2;
    int stride = gridDim.x * blockDim.x;
    for (int gi = blockIdx.x * blockDim.x + threadIdx.x; gi < total; gi += stride) {
        const float* Wg; const float* w; __half* dst; int Cin, idx;
        if (gi < NK1)            { Wg = Wg1;  w = g_w;        dst = g_Acmb1;       Cin = CI; idx = gi; }
        else if (gi < NK1 + NK2) { Wg = Wg2;  w = g_w + 1728; dst = g_A2;          Cin = CO; idx = gi - NK1; }
        else                     { Wg = Wres; w = g_w + 3456; dst = g_Acmb1 + NK1; Cin = CI; idx = gi - NK1 - NK2; }
        int cols = Cin * G_;
        int col = idx % cols, row = idx / cols;
        int a = row / G_, o = row % G_;
        int c = col / G_, g = col % G_;
        float s = 0.f;
        #pragma unroll
        for (int r = 0; r < R_; r++)
            s += Wg[(a * Cin + c) * R_ + r] * w[(o * G_ + g) * R_ + r];
        dst[idx] = __float2half_rn(s);
    }
}

// ---------------- conversion/transpose pass ------------------------------------
// NORM: fuse relu(instnorm) using stage-1 stats read from g_acc (inline finstat)
template <int K, bool NORM, typename Ti>
__global__ void __launch_bounds__(256) convT_kernel(const Ti* __restrict__ src,
                                                    __half* __restrict__ th) {
    __shared__ float tile[32][33];
    int b = blockIdx.z, k0 = blockIdx.y * 32, n0 = blockIdx.x * 32;
    int tx = threadIdx.x, ty = threadIdx.y;   // 32 x 8
    #pragma unroll
    for (int i = 0; i < 4; i++) {
        int k = ty + i * 8;
        float v = (float)src[((size_t)(b * K + k0 + k)) * V_ + n0 + tx];
        if (NORM) {
            int idx = b * CO + (k0 + k) / G_;
            float m_ = g_acc[idx] / CNT1;
            float var = g_acc[64 + idx] / CNT1 - m_ * m_;
            float r_ = rsqrtf(var + 1e-5f);
            v = fmaxf((v - m_) * r_, 0.f);
        }
        tile[k][tx] = v;
    }
    __syncthreads();
    int tid = ty * 32 + tx;
    #pragma unroll
    for (int i = 0; i < 2; i++) {
        int e = tid + i * 256;
        int n = e >> 4, w = e & 15;
        __half2 hh;
        hh.x = __float2half_rn(tile[2 * w][n]);
        hh.y = __float2half_rn(tile[2 * w + 1][n]);
        size_t base = ((size_t)b * V_ + n0 + n) * K + k0 + 2 * w;
        *(__half2*)(th + base) = hh;
    }
}

// ---------------- mma.sync fp16 GEMM: CTA 128x256, warp 64x64, 3-stage --------
#define GST   3
#define ABUF  16384
#define BBUF  32768
#define STAGE (ABUF + BBUF)          // 49152
#define GSMEM (GST * STAGE)          // 147456
template <int K>
__global__ void __launch_bounds__(256) gemm_h(
    const __half* __restrict__ A, const __half* __restrict__ B,
    __half* __restrict__ C0, __half* __restrict__ C1) {
    extern __shared__ char smem[];
    uint32_t sbase = smem_u32(smem);

    int tid = threadIdx.x;
    int lane = tid & 31, warp = tid >> 5;
    int wm = warp >> 2;          // 0..1   (m tile 64)
    int wn = warp & 3;           // 0..3   (n tile 64)
    int b  = blockIdx.z;
    int m0 = blockIdx.y * 128;
    int n0 = blockIdx.x * 256;

    const __half* Bb = B + (size_t)b * V_ * K;
    const int NT = K / 64;

    float acc[4][8][4];
    #pragma unroll
    for (int i = 0; i < 4; i++)
        #pragma unroll
        for (int j = 0; j < 8; j++)
            #pragma unroll
            for (int q = 0; q < 4; q++) acc[i][j][q] = 0.f;

    int lr = tid >> 3, lc = tid & 7;
    uint32_t loff = lr * 128 + ((lc ^ (lr & 7)) << 4);

    auto ldgsts = [&](int ch, int buf) {
        const __half* Ap = A  + ch * 64;
        const __half* Bp = Bb + ch * 64;
        uint32_t ab = sbase + buf * STAGE;
        uint32_t bb = ab + ABUF;
        #pragma unroll
        for (int i = 0; i < 4; i++) {
            int r = lr + i * 32;
            uint32_t off = loff + i * 32 * 128;
            CP_ASYNC16(ab + off, Ap + (size_t)(m0 + r) * K + lc * 8);
        }
        #pragma unroll
        for (int i = 0; i < 8; i++) {
            int r = lr + i * 32;
            uint32_t off = loff + i * 32 * 128;
            CP_ASYNC16(bb + off, Bp + (size_t)(n0 + r) * K + lc * 8);
        }
    };

    ldgsts(0, 0); CP_COMMIT();
    ldgsts(1, 1); CP_COMMIT();

    for (int it = 0; it < NT; it++) {
        CP_WAIT1();
        __syncthreads();
        if (it + 2 < NT) ldgsts(it + 2, (it + 2) % GST);
        CP_COMMIT();

        uint32_t aBuf = sbase + (it % GST) * STAGE;
        uint32_t bBuf = aBuf + ABUF;
        int quad = lane >> 3, l8 = lane & 7;
        #pragma unroll
        for (int kk = 0; kk < 4; kk++) {
            uint32_t af[4][4];
            #pragma unroll
            for (int mt = 0; mt < 4; mt++) {
                int row = wm * 64 + mt * 16 + (lane & 7) + ((lane >> 3) & 1) * 8;
                int cc  = kk * 2 + (lane >> 4);
                uint32_t addr = aBuf + row * 128 + ((cc ^ (row & 7)) << 4);
                LDMATRIX_X4(af[mt][0], af[mt][1], af[mt][2], af[mt][3], addr);
            }
            uint32_t bf[8][2];
            #pragma unroll
            for (int ntp = 0; ntp < 8; ntp += 2) {
                int n = wn * 64 + (ntp + (quad >> 1)) * 8 + l8;
                int cc = kk * 2 + (quad & 1);
                uint32_t addr = bBuf + n * 128 + ((cc ^ (n & 7)) << 4);
                LDMATRIX_X4(bf[ntp][0], bf[ntp][1], bf[ntp + 1][0], bf[ntp + 1][1], addr);
            }
            #pragma unroll
            for (int mt = 0; mt < 4; mt++)
                #pragma unroll
                for (int nt = 0; nt < 8; nt++)
                    MMA_F16(acc[mt][nt][0], acc[mt][nt][1], acc[mt][nt][2], acc[mt][nt][3],
                            af[mt][0], af[mt][1], af[mt][2], af[mt][3],
                            bf[nt][0], bf[nt][1]);
        }
        __syncthreads();
    }

    // epilogue: fp16 stores
    __half* Cb;
    int mloc;
    if (m0 < AO) { Cb = C0 + (size_t)b * AO * V_; mloc = m0; }
    else         { Cb = C1 + (size_t)b * AO * V_; mloc = m0 - AO; }
    int g = lane >> 2, q = lane & 3;
    int mBase = mloc + wm * 64;
    int nBase = n0 + wn * 64;
    #pragma unroll
    for (int mt = 0; mt < 4; mt++) {
        #pragma unroll
        for (int nt = 0; nt < 8; nt++) {
            int row = mBase + mt * 16 + g;
            int col = nBase + nt * 8 + 2 * q;
            __half2 h0 = __floats2half2_rn(acc[mt][nt][0], acc[mt][nt][1]);
            __half2 h1 = __floats2half2_rn(acc[mt][nt][2], acc[mt][nt][3]);
            *(__half2*)(Cb + (size_t)row * V_ + col)       = h0;
            *(__half2*)(Cb + (size_t)(row + 8) * V_ + col) = h1;
        }
    }
}

// ---------------- depthwise conv (8 planes/CTA, vectorized fp16 I/O) ----------
__global__ void __launch_bounds__(256) dwconv_kernel(const __half* __restrict__ src,
                                                     const float* __restrict__ Krot,
                                                     __half* __restrict__ dst,
                                                     float* __restrict__ accSum,
                                                     float* __restrict__ accSq) {
    int dg = blockIdx.x;     // 0..3 (8 planes each)
    int ch = blockIdx.y;     // 0..383
    int b  = blockIdx.z;
    const __half* zin  = src + ((size_t)(b * AO + ch)) * V_;
    __half*       zout = dst + ((size_t)(b * AO + ch)) * V_;

    __shared__ float tile[10][34][34];
    __shared__ float kr[27];
    __shared__ float red[256];

    int tid = threadIdx.x;
    if (tid < 27) kr[tid] = Krot[ch * 27 + tid];

    int z0 = dg * 8;
    for (int e = tid; e < 10 * 132; e += 256) {
        int p = e / 132, i = e % 132;
        if (i < 34)       tile[p][0][i] = 0.f;
        else if (i < 68)  tile[p][33][i - 34] = 0.f;
        else if (i < 100) tile[p][i - 68 + 1][0] = 0.f;
        else              tile[p][i - 100 + 1][33] = 0.f;
    }
    for (int e = tid; e < 1280; e += 256) {
        int p  = e >> 7;
        int idx = e & 127;
        int h  = idx >> 2, w4 = idx & 3;
        int zp = z0 - 1 + p;
        float* drow = &tile[p][h + 1][w4 * 8 + 1];
        if (zp >= 0 && zp < 32) {
            uint4 v = *(const uint4*)(zin + zp * 1024 + h * 32 + w4 * 8);
            const __half2* hp = (const __half2*)&v;
            #pragma unroll
            for (int q = 0; q < 4; q++) {
                float2 f = __half22float2(hp[q]);
                drow[2 * q]     = f.x;
                drow[2 * q + 1] = f.y;
            }
        } else {
            #pragma unroll
            for (int q = 0; q < 8; q++) drow[q] = 0.f;
        }
    }
    __syncthreads();

    float krr[27];
    #pragma unroll
    for (int m = 0; m < 27; m++) krr[m] = kr[m];

    float lsum = 0.f, lsq = 0.f;
    int tx = tid & 31, ty = tid >> 5;   // 32 x 8
    #pragma unroll
    for (int od = 0; od < 8; od++) {
        for (int hh = ty; hh < 32; hh += 8) {
            float a = 0.f;
            #pragma unroll
            for (int p = 0; p < 3; p++)
                #pragma unroll
                for (int i = 0; i < 3; i++)
                    #pragma unroll
                    for (int j = 0; j < 3; j++)
                        a += tile[od + p][hh + i][tx + j] * krr[p * 9 + i * 3 + j];
            zout[(z0 + od) * 1024 + hh * 32 + tx] = __float2half_rn(a);
            lsum += a;
            lsq  += a * a;
        }
    }
    red[tid] = lsum; __syncthreads();
    for (int s = 128; s > 0; s >>= 1) { if (tid < s) red[tid] += red[tid + s]; __syncthreads(); }
    float bs = red[0]; __syncthreads();
    red[tid] = lsq; __syncthreads();
    for (int s = 128; s > 0; s >>= 1) { if (tid < s) red[tid] += red[tid + s]; __syncthreads(); }
    if (tid == 0) {
        int idx = b * CO + ch / G_;
        atomicAdd(&accSum[idx], bs);
        atomicAdd(&accSq[idx],  red[0]);
    }
}

// batchnorm stats of t = relu(instnorm(y2)) + res  (stage-2 stats inline)
__global__ void __launch_bounds__(256) combine_kernel() {
    int br  = blockIdx.x;
    int b   = br / AO;
    int row = br % AO;
    int a   = row / G_;
    int sidx = b * CO + a;
    float mu = g_acc[128 + sidx] / CNT1;
    float var = g_acc[192 + sidx] / CNT1 - mu * mu;
    float rs = rsqrtf(var + 1e-5f);
    const __half2* y2 = (const __half2*)(g_yh   + (size_t)br * V_);
    const __half2* rv = (const __half2*)(g_resh + (size_t)br * V_);
    __shared__ float red[256];
    int tid = threadIdx.x;
    int base2 = blockIdx.y * 1024 + tid * 4;
    float lsum = 0.f, lsq = 0.f;
    #pragma unroll
    for (int q = 0; q < 4; q++) {
        int i2 = base2 + q;
        float2 yv = __half22float2(y2[i2]);
        float2 rr = __half22float2(rv[i2]);
        float ox = fmaxf((yv.x - mu) * rs, 0.f) + rr.x;
        float oy = fmaxf((yv.y - mu) * rs, 0.f) + rr.y;
        lsum += ox + oy;
        lsq  += ox * ox + oy * oy;
    }
    red[tid] = lsum; __syncthreads();
    for (int s = 128; s > 0; s >>= 1) { if (tid < s) red[tid] += red[tid + s]; __syncthreads(); }
    float bs = red[0]; __syncthreads();
    red[tid] = lsq; __syncthreads();
    for (int s = 128; s > 0; s >>= 1) { if (tid < s) red[tid] += red[tid + s]; __syncthreads(); }
    if (tid == 0) {
        atomicAdd(&g_acc[256 + a], bs);
        atomicAdd(&g_acc[288 + a], red[0]);
    }
}

// out = batchnorm(relu(instnorm(y2)) + res), all stats read inline
__global__ void __launch_bounds__(256) final_kernel(float* __restrict__ out,
                                                    const float* __restrict__ gamma,
                                                    const float* __restrict__ beta) {
    int i4 = blockIdx.x * 256 + threadIdx.x;    // 4 elems each; row constant per block
    int row = i4 >> 13;
    int b = row / AO;
    int a = (row % AO) / G_;
    int sidx = b * CO + a;
    float mu = g_acc[128 + sidx] / CNT1;
    float var = g_acc[192 + sidx] / CNT1 - mu * mu;
    float rs = rsqrtf(var + 1e-5f);
    float bmu = g_acc[256 + a] / CNTB;
    float bvar = g_acc[288 + a] / CNTB - bmu * bmu;
    float sc = rsqrtf(bvar + 1e-5f) * gamma[a];
    float bt = beta[a];
    const __half2* y2 = (const __half2*)g_yh;
    const __half2* rv = (const __half2*)g_resh;
    int i2 = i4 * 2;
    float2 ya = __half22float2(y2[i2]),     yb = __half22float2(y2[i2 + 1]);
    float2 ra = __half22float2(rv[i2]),     rb = __half22float2(rv[i2 + 1]);
    float4 o;
    o.x = (fmaxf((ya.x - mu) * rs, 0.f) + ra.x - bmu) * sc + bt;
    o.y = (fmaxf((ya.y - mu) * rs, 0.f) + ra.y - bmu) * sc + bt;
    o.z = (fmaxf((yb.x - mu) * rs, 0.f) + rb.x - bmu) * sc + bt;
    o.w = (fmaxf((yb.y - mu) * rs, 0.f) + rb.y - bmu) * sc + bt;
    ((float4*)out)[i4] = o;
}

// ---------------- launch ------------------------------------------------------
extern "C" void kernel_launch(void* const* d_in, const int* in_sizes, int n_in,
                              void* d_out, int out_size) {
    const float* x      = (const float*)d_in[0];
    const float* H      = (const float*)d_in[1];
    const float* Href1  = (const float*)d_in[2];
    const float* Href2  = (const float*)d_in[3];
    const float* Hrefr  = (const float*)d_in[4];
    const float* Wg1    = (const float*)d_in[5];
    const float* Ws1    = (const float*)d_in[6];
    const float* Wg2    = (const float*)d_in[7];
    const float* Ws2    = (const float*)d_in[8];
    const float* Wres   = (const float*)d_in[9];
    const float* gamma  = (const float*)d_in[10];
    const float* beta   = (const float*)d_in[11];
    float* out = (float*)d_out;

    float *Krot1, *Krot2, *acc;
    __half *Acmb1, *A2, *xt, *yt, *zh, *resh, *yh;
    cudaGetSymbolAddress((void**)&Acmb1, g_Acmb1);
    cudaGetSymbolAddress((void**)&A2,    g_A2);
    cudaGetSymbolAddress((void**)&xt,    g_xt);
    cudaGetSymbolAddress((void**)&yt,    g_yt);
    cudaGetSymbolAddress((void**)&zh,    g_zh);
    cudaGetSymbolAddress((void**)&resh,  g_resh);
    cudaGetSymbolAddress((void**)&yh,    g_yh);
    cudaGetSymbolAddress((void**)&Krot1, g_Krot1);
    cudaGetSymbolAddress((void**)&Krot2, g_Krot2);
    cudaGetSymbolAddress((void**)&acc,   g_acc);

    cudaFuncSetAttribute(gemm_h<KG1>, cudaFuncAttributeMaxDynamicSharedMemorySize, GSMEM);
    cudaFuncSetAttribute(gemm_h<KG2>, cudaFuncAttributeMaxDynamicSharedMemorySize, GSMEM);

    setup_kernel<<<6, 352>>>(H, Href1, Href2, Hrefr, Ws1, Ws2);
    computeK_all<<<1152, 256>>>(Wg1, Wg2, Wres);

    // x -> fp16 transposed [b][v][k]
    convT_kernel<KG1, false, float><<<dim3(1024, 6, 2), dim3(32, 8)>>>(x, xt);

    // fused: [z1 ; res] = [K1 ; Kres] @ x   (M = 768)
    gemm_h<KG1><<<dim3(128, 6, 2), 256, GSMEM>>>(Acmb1, xt, zh, resh);
    // y1 = dwconv(z1) + stage-1 stats
    dwconv_kernel<<<dim3(4, 384, 2), 256>>>(zh, Krot1, yh, acc + 0, acc + 64);
    // relu(instnorm(y1)) -> fp16 transposed (stats inline)
    convT_kernel<KG2, true, __half><<<dim3(1024, 12, 2), dim3(32, 8)>>>(yh, yt);
    // z2 = K2 @ (.)
    gemm_h<KG2><<<dim3(128, 3, 2), 256, GSMEM>>>(A2, yt, zh, zh);
    // y2 = dwconv(z2) + stage-2 stats
    dwconv_kernel<<<dim3(4, 384, 2), 256>>>(zh, Krot2, yh, acc + 128, acc + 192);
    // batchnorm stats of t (stats inline, no materialization)
    combine_kernel<<<dim3(768, 16), 256>>>();
    // out = batchnorm(relu(instnorm(y2)) + res)
    final_kernel<<<24576, 256>>>(out, gamma, beta);
    cudaMemcpyAsync(out + NY, H, 108 * sizeof(float), cudaMemcpyDeviceToDevice);
}

// round 14
// speedup vs baseline: 1.0489x; 1.0489x over previous
#include <cuda_runtime.h>
#include <cuda_fp16.h>
#include <cstdint>
#include <math.h>

// Problem constants
#define B_   2
#define CI   16
#define CO   32
#define G_   12
#define R_   12
#define S_   32
#define V_   32768          // 32^3
#define AO   384            // Co*G
#define KG1  192            // Ci*G
#define KG2  384            // Co*G
#define NY   25165824       // B*Co*G*V  (y element count)
#define CNT1 393216.0f      // G_*V_
#define CNTB 786432.0f      // B_*G_*V_

// ---------------- scratch (device globals; no allocation allowed) -------------
__device__ __half g_zh[(size_t)B_ * AO * V_];        // z1 / z2
__device__ __half g_resh[(size_t)B_ * AO * V_];      // residual
__device__ __half g_yh[(size_t)B_ * AO * V_];        // y1 / y2
__device__ float  g_w[3 * 144 * R_];
__device__ __half g_Acmb1[2 * AO * KG1];             // [K1 ; Kres]  (768 x 192)
__device__ __half g_A2[AO * KG2];                    // 384 x 384
__device__ __half g_xt[(size_t)B_ * V_ * KG1];       // x transposed fp16 [b][v][k]
__device__ __half g_yt[(size_t)B_ * V_ * KG2];       // norm(relu(y1)) transposed fp16
__device__ float  g_Krot1[AO * 27];
__device__ float  g_Krot2[AO * 27];
__device__ float  g_acc[320];  // [0:64) s1 [64:128) q1 [128:192) s2 [192:256) q2 [256:288) bs [288:320) bq

// ---------------- helpers ------------------------------------------------------
__device__ __forceinline__ uint32_t smem_u32(const void* p) {
    uint32_t a;
    asm("{ .reg .u64 t; cvta.to.shared.u64 t, %1; cvt.u32.u64 %0, t; }" : "=r"(a) : "l"(p));
    return a;
}

#define LDMATRIX_X4(r0, r1, r2, r3, addr) \
    asm volatile("ldmatrix.sync.aligned.m8n8.x4.shared.b16 {%0,%1,%2,%3}, [%4];" \
                 : "=r"(r0), "=r"(r1), "=r"(r2), "=r"(r3) : "r"(addr))
#define MMA_F16(c0, c1, c2, c3, a0, a1, a2, a3, b0, b1) \
    asm volatile("mma.sync.aligned.m16n8k16.row.col.f32.f16.f16.f32 " \
                 "{%0,%1,%2,%3}, {%4,%5,%6,%7}, {%8,%9}, {%0,%1,%2,%3};" \
                 : "+f"(c0), "+f"(c1), "+f"(c2), "+f"(c3) \
                 : "r"(a0), "r"(a1), "r"(a2), "r"(a3), "r"(b0), "r"(b1))
#define CP_ASYNC16(dst, src) \
    asm volatile("cp.async.cg.shared.global [%0], [%1], 16;" :: "r"(dst), "l"(src))
#define CP_COMMIT() asm volatile("cp.async.commit_group;" ::: "memory")
#define CP_WAIT1()  asm volatile("cp.async.wait_group 1;" ::: "memory")

// ---------------- merged setup kernel -----------------------------------------
__global__ void setup_kernel(const float* __restrict__ H,
                             const float* __restrict__ Href1,
                             const float* __restrict__ Href2,
                             const float* __restrict__ Hrefr,
                             const float* __restrict__ Ws1,
                             const float* __restrict__ Ws2) {
    int blk = blockIdx.x;
    int t = threadIdx.x;
    if (blk < 3) {
        if (t >= 144) return;
        const float* Href = (blk == 0) ? Href1 : (blk == 1) ? Href2 : Hrefr;
        float* wout = g_w + blk * 1728;
        int o = t / G_, g = t % G_;
        float M[9];
        #pragma unroll
        for (int i = 0; i < 3; i++)
            #pragma unroll
            for (int k = 0; k < 3; k++) {
                float s = 0.f;
                #pragma unroll
                for (int j = 0; j < 3; j++)
                    s += H[o*9 + j*3 + i] * H[g*9 + j*3 + k];
                M[i*3 + k] = s;
            }
        float wv[R_]; float tot = 0.f;
        #pragma unroll
        for (int r = 0; r < R_; r++) {
            float tr = 0.f;
            #pragma unroll
            for (int m = 0; m < 9; m++) tr += M[m] * Href[r*9 + m];
            float c = (tr - 1.f) * 0.5f;
            c = fminf(fmaxf(c, -1.f + 1e-6f), 1.f - 1e-6f);
            float d = acosf(c);
            float ww = expf(-2.f * d * d);
            wv[r] = ww; tot += ww;
        }
        float inv = 1.f / tot;
        #pragma unroll
        for (int r = 0; r < R_; r++) wout[t * R_ + r] = wv[r] * inv;
    } else if (blk < 5) {
        if (t >= G_ * 27) return;
        const float* Ws = (blk == 3) ? Ws1 : Ws2;
        float* Krot = (blk == 3) ? g_Krot1 : g_Krot2;
        int g = t / 27, v = t % 27;
        int d = v / 9, h = (v / 3) % 3, w = v % 3;
        float cz = (float)(d - 1), cy = (float)(h - 1), cx = (float)(w - 1);
        float pix[3];
        #pragma unroll
        for (int j = 0; j < 3; j++)
            pix[j] = cz * H[g*9 + 0*3 + j] + cy * H[g*9 + 1*3 + j] + cx * H[g*9 + 2*3 + j] + 1.0f;
        float tt[3]; int fi[3];
        #pragma unroll
        for (int j = 0; j < 3; j++) {
            float f = floorf(pix[j]);
            tt[j] = pix[j] - f;
            fi[j] = (int)f;
        }
        float wc[8]; int ic[8];
        int n = 0;
        #pragma unroll
        for (int dz = 0; dz < 2; dz++)
            #pragma unroll
            for (int dy = 0; dy < 2; dy++)
                #pragma unroll
                for (int dx = 0; dx < 2; dx++) {
                    int iz = fi[0] + dz, iy = fi[1] + dy, ix = fi[2] + dx;
                    bool valid = (iz >= 0 && iz <= 2 && iy >= 0 && iy <= 2 && ix >= 0 && ix <= 2);
                    float wz = dz ? tt[0] : 1.f - tt[0];
                    float wy = dy ? tt[1] : 1.f - tt[1];
                    float wx = dx ? tt[2] : 1.f - tt[2];
                    int cz_ = min(max(iz, 0), 2), cy_ = min(max(iy, 0), 2), cx_ = min(max(ix, 0), 2);
                    ic[n] = cz_*9 + cy_*3 + cx_;
                    wc[n] = valid ? (wz * wy * wx) : 0.f;
                    n++;
                }
        for (int c = 0; c < CO; c++) {
            float s = 0.f;
            #pragma unroll
            for (int q = 0; q < 8; q++) s += Ws[c*27 + ic[q]] * wc[q];
            Krot[(c * G_ + g) * 27 + v] = s;
        }
    } else {
        if (t < 320) g_acc[t] = 0.f;
    }
}

// merged K-matrix build
#define NK1 (AO * KG1)
#define NK2 (AO * KG2)
__global__ void computeK_all(const float* __restrict__ Wg1,
                             const float* __restrict__ Wg2,
                             const float* __restrict__ Wres) {
    int total = 2 * NK1 + NK2;
    int stride = gridDim.x * blockDim.x;
    for (int gi = blockIdx.x * blockDim.x + threadIdx.x; gi < total; gi += stride) {
        const float* Wg; const float* w; __half* dst; int Cin, idx;
        if (gi < NK1)            { Wg = Wg1;  w = g_w;        dst = g_Acmb1;       Cin = CI; idx = gi; }
        else if (gi < NK1 + NK2) { Wg = Wg2;  w = g_w + 1728; dst = g_A2;          Cin = CO; idx = gi - NK1; }
        else                     { Wg = Wres; w = g_w + 3456; dst = g_Acmb1 + NK1; Cin = CI; idx = gi - NK1 - NK2; }
        int cols = Cin * G_;
        int col = idx % cols, row = idx / cols;
        int a = row / G_, o = row % G_;
        int c = col / G_, g = col % G_;
        float s = 0.f;
        #pragma unroll
        for (int r = 0; r < R_; r++)
            s += Wg[(a * Cin + c) * R_ + r] * w[(o * G_ + g) * R_ + r];
        dst[idx] = __float2half_rn(s);
    }
}

// ---------------- conversion/transpose pass ------------------------------------
// NORM: fuse relu(instnorm) using stage-1 stats read from g_acc (inline finstat)
template <int K, bool NORM, typename Ti>
__global__ void __launch_bounds__(256) convT_kernel(const Ti* __restrict__ src,
                                                    __half* __restrict__ th) {
    __shared__ float tile[32][33];
    int b = blockIdx.z, k0 = blockIdx.y * 32, n0 = blockIdx.x * 32;
    int tx = threadIdx.x, ty = threadIdx.y;   // 32 x 8
    #pragma unroll
    for (int i = 0; i < 4; i++) {
        int k = ty + i * 8;
        float v = (float)src[((size_t)(b * K + k0 + k)) * V_ + n0 + tx];
        if (NORM) {
            int idx = b * CO + (k0 + k) / G_;
            float m_ = g_acc[idx] / CNT1;
            float var = g_acc[64 + idx] / CNT1 - m_ * m_;
            float r_ = rsqrtf(var + 1e-5f);
            v = fmaxf((v - m_) * r_, 0.f);
        }
        tile[k][tx] = v;
    }
    __syncthreads();
    int tid = ty * 32 + tx;
    #pragma unroll
    for (int i = 0; i < 2; i++) {
        int e = tid + i * 256;
        int n = e >> 4, w = e & 15;
        __half2 hh;
        hh.x = __float2half_rn(tile[2 * w][n]);
        hh.y = __float2half_rn(tile[2 * w + 1][n]);
        size_t base = ((size_t)b * V_ + n0 + n) * K + k0 + 2 * w;
        *(__half2*)(th + base) = hh;
    }
}

// ---------------- mma.sync fp16 GEMM: CTA 128x128, warp 64x32, 3-stage --------
#define GST   3
#define GBUF  32768
#define GSMEM (GST * GBUF)
template <int K>
__global__ void __launch_bounds__(256) gemm_h(
    const __half* __restrict__ A, const __half* __restrict__ B,
    __half* __restrict__ C0, __half* __restrict__ C1) {
    extern __shared__ char smem[];
    uint32_t sbase = smem_u32(smem);

    int tid = threadIdx.x;
    int lane = tid & 31, warp = tid >> 5;
    int wm = warp >> 2;          // 0..1
    int wn = warp & 3;           // 0..3
    int b  = blockIdx.z;
    int m0 = blockIdx.y * 128;
    int n0 = blockIdx.x * 128;

    const __half* Bb = B + (size_t)b * V_ * K;
    const int NT = K / 64;

    float acc[4][4][4];
    #pragma unroll
    for (int i = 0; i < 4; i++)
        #pragma unroll
        for (int j = 0; j < 4; j++)
            #pragma unroll
            for (int q = 0; q < 4; q++) acc[i][j][q] = 0.f;

    int lr = tid >> 3, lc = tid & 7;
    uint32_t loff = lr * 128 + ((lc ^ (lr & 7)) << 4);

    auto ldgsts = [&](int ch, int buf) {
        const __half* Ap = A  + ch * 64;
        const __half* Bp = Bb + ch * 64;
        uint32_t base = sbase + buf * GBUF;
        #pragma unroll
        for (int i = 0; i < 4; i++) {
            int r = lr + i * 32;
            uint32_t off = loff + i * 32 * 128;
            CP_ASYNC16(base + off,         Ap + (size_t)(m0 + r) * K + lc * 8);
            CP_ASYNC16(base + 16384 + off, Bp + (size_t)(n0 + r) * K + lc * 8);
        }
    };

    ldgsts(0, 0); CP_COMMIT();
    ldgsts(1, 1); CP_COMMIT();

    for (int it = 0; it < NT; it++) {
        CP_WAIT1();
        __syncthreads();
        if (it + 2 < NT) ldgsts(it + 2, (it + 2) % GST);
        CP_COMMIT();

        uint32_t aBuf = sbase + (it % GST) * GBUF;
        uint32_t bBuf = aBuf + 16384;
        int quad = lane >> 3, l8 = lane & 7;
        #pragma unroll
        for (int kk = 0; kk < 4; kk++) {
            uint32_t af[4][4];
            #pragma unroll
            for (int mt = 0; mt < 4; mt++) {
                int row = wm * 64 + mt * 16 + (lane & 7) + ((lane >> 3) & 1) * 8;
                int cc  = kk * 2 + (lane >> 4);
                uint32_t addr = aBuf + row * 128 + ((cc ^ (row & 7)) << 4);
                LDMATRIX_X4(af[mt][0], af[mt][1], af[mt][2], af[mt][3], addr);
            }
            uint32_t bf[4][2];
            #pragma unroll
            for (int ntp = 0; ntp < 4; ntp += 2) {
                int n = wn * 32 + (ntp + (quad >> 1)) * 8 + l8;
                int cc = kk * 2 + (quad & 1);
                uint32_t addr = bBuf + n * 128 + ((cc ^ (n & 7)) << 4);
                LDMATRIX_X4(bf[ntp][0], bf[ntp][1], bf[ntp + 1][0], bf[ntp + 1][1], addr);
            }
            #pragma unroll
            for (int mt = 0; mt < 4; mt++)
                #pragma unroll
                for (int nt = 0; nt < 4; nt++)
                    MMA_F16(acc[mt][nt][0], acc[mt][nt][1], acc[mt][nt][2], acc[mt][nt][3],
                            af[mt][0], af[mt][1], af[mt][2], af[mt][3],
                            bf[nt][0], bf[nt][1]);
        }
        __syncthreads();
    }

    // epilogue: fp16 stores
    __half* Cb;
    int mloc;
    if (m0 < AO) { Cb = C0 + (size_t)b * AO * V_; mloc = m0; }
    else         { Cb = C1 + (size_t)b * AO * V_; mloc = m0 - AO; }
    int g = lane >> 2, q = lane & 3;
    int mBase = mloc + wm * 64;
    int nBase = n0 + wn * 32;
    #pragma unroll
    for (int mt = 0; mt < 4; mt++) {
        #pragma unroll
        for (int nt = 0; nt < 4; nt++) {
            int row = mBase + mt * 16 + g;
            int col = nBase + nt * 8 + 2 * q;
            __half2 h0 = __floats2half2_rn(acc[mt][nt][0], acc[mt][nt][1]);
            __half2 h1 = __floats2half2_rn(acc[mt][nt][2], acc[mt][nt][3]);
            *(__half2*)(Cb + (size_t)row * V_ + col)       = h0;
            *(__half2*)(Cb + (size_t)(row + 8) * V_ + col) = h1;
        }
    }
}

// ---------------- depthwise conv (8 planes/CTA, vectorized fp16 I/O) ----------
__global__ void __launch_bounds__(256) dwconv_kernel(const __half* __restrict__ src,
                                                     const float* __restrict__ Krot,
                                                     __half* __restrict__ dst,
                                                     float* __restrict__ accSum,
                                                     float* __restrict__ accSq) {
    int dg = blockIdx.x;     // 0..3 (8 planes each)
    int ch = blockIdx.y;     // 0..383
    int b  = blockIdx.z;
    const __half* zin  = src + ((size_t)(b * AO + ch)) * V_;
    __half*       zout = dst + ((size_t)(b * AO + ch)) * V_;

    __shared__ float tile[10][34][34];
    __shared__ float kr[27];
    __shared__ float red[256];

    int tid = threadIdx.x;
    if (tid < 27) kr[tid] = Krot[ch * 27 + tid];

    int z0 = dg * 8;
    for (int e = tid; e < 10 * 132; e += 256) {
        int p = e / 132, i = e % 132;
        if (i < 34)       tile[p][0][i] = 0.f;
        else if (i < 68)  tile[p][33][i - 34] = 0.f;
        else if (i < 100) tile[p][i - 68 + 1][0] = 0.f;
        else              tile[p][i - 100 + 1][33] = 0.f;
    }
    for (int e = tid; e < 1280; e += 256) {
        int p  = e >> 7;
        int idx = e & 127;
        int h  = idx >> 2, w4 = idx & 3;
        int zp = z0 - 1 + p;
        float* drow = &tile[p][h + 1][w4 * 8 + 1];
        if (zp >= 0 && zp < 32) {
            uint4 v = *(const uint4*)(zin + zp * 1024 + h * 32 + w4 * 8);
            const __half2* hp = (const __half2*)&v;
            #pragma unroll
            for (int q = 0; q < 4; q++) {
                float2 f = __half22float2(hp[q]);
                drow[2 * q]     = f.x;
                drow[2 * q + 1] = f.y;
            }
        } else {
            #pragma unroll
            for (int q = 0; q < 8; q++) drow[q] = 0.f;
        }
    }
    __syncthreads();

    float krr[27];
    #pragma unroll
    for (int m = 0; m < 27; m++) krr[m] = kr[m];

    float lsum = 0.f, lsq = 0.f;
    int tx = tid & 31, ty = tid >> 5;   // 32 x 8
    #pragma unroll
    for (int od = 0; od < 8; od++) {
        for (int hh = ty; hh < 32; hh += 8) {
            float a = 0.f;
            #pragma unroll
            for (int p = 0; p < 3; p++)
                #pragma unroll
                for (int i = 0; i < 3; i++)
                    #pragma unroll
                    for (int j = 0; j < 3; j++)
                        a += tile[od + p][hh + i][tx + j] * krr[p * 9 + i * 3 + j];
            zout[(z0 + od) * 1024 + hh * 32 + tx] = __float2half_rn(a);
            lsum += a;
            lsq  += a * a;
        }
    }
    red[tid] = lsum; __syncthreads();
    for (int s = 128; s > 0; s >>= 1) { if (tid < s) red[tid] += red[tid + s]; __syncthreads(); }
    float bs = red[0]; __syncthreads();
    red[tid] = lsq; __syncthreads();
    for (int s = 128; s > 0; s >>= 1) { if (tid < s) red[tid] += red[tid + s]; __syncthreads(); }
    if (tid == 0) {
        int idx = b * CO + ch / G_;
        atomicAdd(&accSum[idx], bs);
        atomicAdd(&accSq[idx],  red[0]);
    }
}

// batchnorm stats of t = relu(instnorm(y2)) + res  (stage-2 stats inline)
__global__ void __launch_bounds__(256) combine_kernel() {
    int br  = blockIdx.x;
    int b   = br / AO;
    int row = br % AO;
    int a   = row / G_;
    int sidx = b * CO + a;
    float mu = g_acc[128 + sidx] / CNT1;
    float var = g_acc[192 + sidx] / CNT1 - mu * mu;
    float rs = rsqrtf(var + 1e-5f);
    const __half2* y2 = (const __half2*)(g_yh   + (size_t)br * V_);
    const __half2* rv = (const __half2*)(g_resh + (size_t)br * V_);
    __shared__ float red[256];
    int tid = threadIdx.x;
    int base2 = blockIdx.y * 1024 + tid * 4;
    float lsum = 0.f, lsq = 0.f;
    #pragma unroll
    for (int q = 0; q < 4; q++) {
        int i2 = base2 + q;
        float2 yv = __half22float2(y2[i2]);
        float2 rr = __half22float2(rv[i2]);
        float ox = fmaxf((yv.x - mu) * rs, 0.f) + rr.x;
        float oy = fmaxf((yv.y - mu) * rs, 0.f) + rr.y;
        lsum += ox + oy;
        lsq  += ox * ox + oy * oy;
    }
    red[tid] = lsum; __syncthreads();
    for (int s = 128; s > 0; s >>= 1) { if (tid < s) red[tid] += red[tid + s]; __syncthreads(); }
    float bs = red[0]; __syncthreads();
    red[tid] = lsq; __syncthreads();
    for (int s = 128; s > 0; s >>= 1) { if (tid < s) red[tid] += red[tid + s]; __syncthreads(); }
    if (tid == 0) {
        atomicAdd(&g_acc[256 + a], bs);
        atomicAdd(&g_acc[288 + a], red[0]);
    }
}

// out = batchnorm(relu(instnorm(y2)) + res), all stats read inline
__global__ void __launch_bounds__(256) final_kernel(float* __restrict__ out,
                                                    const float* __restrict__ gamma,
                                                    const float* __restrict__ beta) {
    int i4 = blockIdx.x * 256 + threadIdx.x;
    int row = i4 >> 13;
    int b = row / AO;
    int a = (row % AO) / G_;
    int sidx = b * CO + a;
    float mu = g_acc[128 + sidx] / CNT1;
    float var = g_acc[192 + sidx] / CNT1 - mu * mu;
    float rs = rsqrtf(var + 1e-5f);
    float bmu = g_acc[256 + a] / CNTB;
    float bvar = g_acc[288 + a] / CNTB - bmu * bmu;
    float sc = rsqrtf(bvar + 1e-5f) * gamma[a];
    float bt = beta[a];
    const __half2* y2 = (const __half2*)g_yh;
    const __half2* rv = (const __half2*)g_resh;
    int i2 = i4 * 2;
    float2 ya = __half22float2(y2[i2]),     yb = __half22float2(y2[i2 + 1]);
    float2 ra = __half22float2(rv[i2]),     rb = __half22float2(rv[i2 + 1]);
    float4 o;
    o.x = (fmaxf((ya.x - mu) * rs, 0.f) + ra.x - bmu) * sc + bt;
    o.y = (fmaxf((ya.y - mu) * rs, 0.f) + ra.y - bmu) * sc + bt;
    o.z = (fmaxf((yb.x - mu) * rs, 0.f) + rb.x - bmu) * sc + bt;
    o.w = (fmaxf((yb.y - mu) * rs, 0.f) + rb.y - bmu) * sc + bt;
    ((float4*)out)[i4] = o;
}

// ---------------- launch ------------------------------------------------------
extern "C" void kernel_launch(void* const* d_in, const int* in_sizes, int n_in,
                              void* d_out, int out_size) {
    const float* x      = (const float*)d_in[0];
    const float* H      = (const float*)d_in[1];
    const float* Href1  = (const float*)d_in[2];
    const float* Href2  = (const float*)d_in[3];
    const float* Hrefr  = (const float*)d_in[4];
    const float* Wg1    = (const float*)d_in[5];
    const float* Ws1    = (const float*)d_in[6];
    const float* Wg2    = (const float*)d_in[7];
    const float* Ws2    = (const float*)d_in[8];
    const float* Wres   = (const float*)d_in[9];
    const float* gamma  = (const float*)d_in[10];
    const float* beta   = (const float*)d_in[11];
    float* out = (float*)d_out;

    float *Krot1, *Krot2, *acc;
    __half *Acmb1, *A2, *xt, *yt, *zh, *resh, *yh;
    cudaGetSymbolAddress((void**)&Acmb1, g_Acmb1);
    cudaGetSymbolAddress((void**)&A2,    g_A2);
    cudaGetSymbolAddress((void**)&xt,    g_xt);
    cudaGetSymbolAddress((void**)&yt,    g_yt);
    cudaGetSymbolAddress((void**)&zh,    g_zh);
    cudaGetSymbolAddress((void**)&resh,  g_resh);
    cudaGetSymbolAddress((void**)&yh,    g_yh);
    cudaGetSymbolAddress((void**)&Krot1, g_Krot1);
    cudaGetSymbolAddress((void**)&Krot2, g_Krot2);
    cudaGetSymbolAddress((void**)&acc,   g_acc);

    cudaFuncSetAttribute(gemm_h<KG1>, cudaFuncAttributeMaxDynamicSharedMemorySize, GSMEM);
    cudaFuncSetAttribute(gemm_h<KG2>, cudaFuncAttributeMaxDynamicSharedMemorySize, GSMEM);

    setup_kernel<<<6, 352>>>(H, Href1, Href2, Hrefr, Ws1, Ws2);
    computeK_all<<<1152, 256>>>(Wg1, Wg2, Wres);

    // x -> fp16 transposed [b][v][k]
    convT_kernel<KG1, false, float><<<dim3(1024, 6, 2), dim3(32, 8)>>>(x, xt);

    // fused: [z1 ; res] = [K1 ; Kres] @ x   (M = 768)
    gemm_h<KG1><<<dim3(256, 6, 2), 256, GSMEM>>>(Acmb1, xt, zh, resh);
    // y1 = dwconv(z1) + stage-1 stats
    dwconv_kernel<<<dim3(4, 384, 2), 256>>>(zh, Krot1, yh, acc + 0, acc + 64);
    // relu(instnorm(y1)) -> fp16 transposed (stats inline)
    convT_kernel<KG2, true, __half><<<dim3(1024, 12, 2), dim3(32, 8)>>>(yh, yt);
    // z2 = K2 @ (.)
    gemm_h<KG2><<<dim3(256, 3, 2), 256, GSMEM>>>(A2, yt, zh, zh);
    // y2 = dwconv(z2) + stage-2 stats
    dwconv_kernel<<<dim3(4, 384, 2), 256>>>(zh, Krot2, yh, acc + 128, acc + 192);
    // batchnorm stats of t (stats inline, no materialization)
    combine_kernel<<<dim3(768, 16), 256>>>();
    // out = batchnorm(relu(instnorm(y2)) + res)
    final_kernel<<<24576, 256>>>(out, gamma, beta);
    cudaMemcpyAsync(out + NY, H, 108 * sizeof(float), cudaMemcpyDeviceToDevice);
}